// round 14
// baseline (speedup 1.0000x reference)
#include <cuda_runtime.h>
#include <cuda_bf16.h>
#include <cstdint>

// DynamicRelationshipExtractor — GB300 sm_103a, round 14
// = round 13 algorithm restructured for 2 CTAs/SM:
//   TP=32 pairs, NT=256 (8 warps), grid 63x64 (no tail), smem 105.6KB/CTA.
//   xs dropped (feats reads x from L2), 2 WS buffers with per-phase role swap,
//   W1(k+1) prefetched in S4, hid panels alias dead prologue smem.

#define EPSF 1e-6f
#define NT 256

static const int NC = 64;
static const int Dd = 128;
static const int Pp = 2016;
static const int TP = 32;

typedef unsigned long long u64;
typedef unsigned int u32;

__device__ __forceinline__ void mma16816(float* c, u32 a0, u32 a1, u32 a2, u32 a3,
                                         u32 b0, u32 b1) {
    asm volatile(
        "mma.sync.aligned.m16n8k16.row.col.f32.bf16.bf16.f32 "
        "{%0,%1,%2,%3},{%4,%5,%6,%7},{%8,%9},{%0,%1,%2,%3};"
        : "+f"(c[0]), "+f"(c[1]), "+f"(c[2]), "+f"(c[3])
        : "r"(a0), "r"(a1), "r"(a2), "r"(a3), "r"(b0), "r"(b1));
}

__device__ __forceinline__ void split2(float a, float b, u32 &hp, u32 &lp) {
    __nv_bfloat16 ha = __float2bfloat16(a), hb_ = __float2bfloat16(b);
    __nv_bfloat16 la = __float2bfloat16(a - __bfloat162float(ha));
    __nv_bfloat16 lb = __float2bfloat16(b - __bfloat162float(hb_));
    hp = ((u32)__bfloat16_as_ushort(hb_) << 16) | (u32)__bfloat16_as_ushort(ha);
    lp = ((u32)__bfloat16_as_ushort(lb)  << 16) | (u32)__bfloat16_as_ushort(la);
}

__device__ __forceinline__ u32 smem_u32(const void* p) {
    u32 a; asm("{ .reg .u64 t; cvta.to.shared.u64 t, %1; cvt.u32.u64 %0, t; }" : "=r"(a) : "l"(p));
    return a;
}
__device__ __forceinline__ void cpa16(u32 dst, const void* src) {
    asm volatile("cp.async.cg.shared.global [%0], [%1], 16;"
                 :: "r"(dst), "l"(__cvta_generic_to_global(src)));
}
#define CPA_COMMIT() asm volatile("cp.async.commit_group;" ::: "memory")
#define CPA_WAIT0()  asm volatile("cp.async.wait_group 0;" ::: "memory")

// precomputed weight images (bf16 hi/lo, B-operand [n][k] layouts)
__device__ __align__(16) __nv_bfloat16 g_ow1t[6][2][8192];   // W1^T: [64 n(j)][128 k(d)]
__device__ __align__(16) __nv_bfloat16 g_gt[8][2][16384];    // G_k^T: [256 n(q)][64 k(j)]
__device__ __align__(16) __nv_bfloat16 g_fw2t[2][32768];     // fW2^T: [128 n(d)][256 k(q)]
__device__ float g_csum[256];                                 // sum_k b2@fW1_k

__global__ void conv_kernel(const float* __restrict__ fW1,
                            const float* __restrict__ oW1,
                            const float* __restrict__ oW2,
                            const float* __restrict__ ob2,
                            const float* __restrict__ fW2) {
    const int mlp_idx[8] = {0, 1, 2, 3, 4, 4, 5, 5};
    int idx = blockIdx.x * blockDim.x + threadIdx.x;   // 0..262143

    // G_k[j][q] = sum_d W2[w(k)][j][d] * fW1[k*128+d][q], stored ^T [q][j]
    if (idx < 131072) {
        int kidx = idx >> 14;
        int e = idx & 16383;
        int q = e & 255, j = e >> 8;
        int w = mlp_idx[kidx];
        const float* w2row = oW2 + (size_t)w*8192 + j*128;
        const float* f1col = fW1 + (size_t)kidx*128*256 + q;
        float s = 0.f;
        #pragma unroll 8
        for (int d = 0; d < 128; d++) s = fmaf(w2row[d], f1col[(size_t)d*256], s);
        __nv_bfloat16 hi = __float2bfloat16(s);
        __nv_bfloat16 lo = __float2bfloat16(s - __bfloat162float(hi));
        g_gt[kidx][0][q*64 + j] = hi;
        g_gt[kidx][1][q*64 + j] = lo;
    }
    if (idx < 49152) {
        int w = idx >> 13;
        int e = idx & 8191;
        int n = e >> 7, kk = e & 127;       // n=j, k=d
        float v = oW1[(size_t)w*8192 + kk*64 + n];
        __nv_bfloat16 hi = __float2bfloat16(v);
        __nv_bfloat16 lo = __float2bfloat16(v - __bfloat162float(hi));
        g_ow1t[w][0][n*128 + kk] = hi;
        g_ow1t[w][1][n*128 + kk] = lo;
    }
    if (idx < 32768) {
        int n = idx >> 8, kk = idx & 255;   // n=d(128), k=q(256)
        float v = fW2[(size_t)kk*128 + n];
        __nv_bfloat16 hi = __float2bfloat16(v);
        __nv_bfloat16 lo = __float2bfloat16(v - __bfloat162float(hi));
        g_fw2t[0][n*256 + kk] = hi;
        g_fw2t[1][n*256 + kk] = lo;
    }
    if (idx < 256) {
        int q = idx;
        float s = 0.f;
        for (int kk = 0; kk < 8; kk++) {
            int w = mlp_idx[kk];
            const float* b2r = ob2 + w*128;
            const float* f1c = fW1 + (size_t)kk*128*256 + q;
            #pragma unroll 8
            for (int d = 0; d < 128; d++) s = fmaf(b2r[d], f1c[(size_t)d*256], s);
        }
        g_csum[q] = s;
    }
}

// ---- shared layout (BYTE offsets), per-CTA total 108160 (105.6KB) ----
#define OFF_FH     0          // [32][136] bf16 = 8704
#define OFF_FL     8704       // -> 17408
#define OFF_HH     17408      // [32][72] bf16 = 4608
#define OFF_HL     22016      // -> 26624
#define OFF_PCON   26624      // 1024 fl -> 30720
#define OFF_PTOK4  30720      // 512 fl -> 32768
#define OFF_PH4    32768      // 256 fl -> 33792
#define OFF_INORM  33792      // 64 fl -> 34048
#define OFF_INTS   34048      // 3*32 int -> 34432
#define OFF_WS0    34432      // 36864 -> 71296
#define OFF_WS1    71296      // 36864 -> 108160
#define SMEM_BYTES 108160
// hid bf16 panels alias [0, 34048) after k-loop: hi [32][264] at 0, lo at 16896
#define OFF_HIDH   0
#define OFF_HIDL   16896

__device__ __forceinline__ float featf(int k, float a, float c, float ni, float nj) {
    switch (k) {
        case 0: return a * c;
        case 1: return a + c;
        case 2: return (a * ni) * (c * nj);
        case 3: return fabsf(a - c);
        case 4: return a - c;
        case 5: return c - a;
        case 6: return __fdiv_rn(a, c + EPSF);
        default: return __fdiv_rn(c, a + EPSF);
    }
}

__global__ void __launch_bounds__(NT, 2)
dre_kernel(const float* __restrict__ x, const int* __restrict__ presence,
           const int* __restrict__ idx_i, const int* __restrict__ idx_j,
           const float* __restrict__ oW1, const float* __restrict__ ob1,
           const float* __restrict__ oW2, const float* __restrict__ ob2,
           const float* __restrict__ pW1, const float* __restrict__ pb1,
           const float* __restrict__ pW2, const float* __restrict__ pb2,
           const float* __restrict__ fW1, const float* __restrict__ fb1,
           const float* __restrict__ fW2, const float* __restrict__ fb2,
           float* __restrict__ out)
{
    extern __shared__ float sm[];
    char*  smc   = (char*)sm;
    u32*   fhw   = (u32*)(smc + OFF_FH);
    u32*   flw   = (u32*)(smc + OFF_FL);
    u32*   hhw   = (u32*)(smc + OFF_HH);
    u32*   hlw   = (u32*)(smc + OFF_HL);
    float* pcon  = (float*)(smc + OFF_PCON);
    float* ptok4 = (float*)(smc + OFF_PTOK4);
    float* ph4   = (float*)(smc + OFF_PH4);
    float* inorm = (float*)(smc + OFF_INORM);
    int*   pi    = (int*)(smc + OFF_INTS);
    int*   pj    = pi + 32;
    int*   pcx   = pj + 32;

    const int tid = threadIdx.x;
    const int b   = blockIdx.y;
    const int p0  = blockIdx.x * TP;
    const int wid = tid >> 5, lane = tid & 31;
    const int g   = lane >> 2;          // frag row group 0..7
    const int t   = lane & 3;           // frag k-word 0..3
    const int t2  = t * 2;
    const u32 sb  = smem_u32(sm);
    const float* xb = x + (size_t)b * NC * Dd;

    const int mlp_idx[8] = {0, 1, 2, 3, 4, 4, 5, 5};

    // ---- prologue: pairs, ph4, prefetch W1(0) -> WS0 ----
    if (tid < TP) {
        int pp = p0 + tid;
        int ii = idx_i[pp], jj = idx_j[pp];
        pi[tid] = ii; pj[tid] = jj;
        int pa = presence[b*NC + ii], pb_ = presence[b*NC + jj];
        pcx[tid] = pa ? (pb_ ? 0 : 1) : (pb_ ? 2 : 3);
    }
    {
        int c = tid >> 6, tt = tid & 63;
        float v = pW1[c*64 + tt] + pb1[tt];
        ph4[tid] = v > 0.f ? v : 0.f;
    }
    #pragma unroll
    for (int i = 0; i < 8; i++) {
        int idx = tid + i*NT;               // 0..2047
        int c = idx >> 10, e = idx & 1023;
        int n = e >> 4, c8 = e & 15;
        cpa16(sb + OFF_WS0 + c*17408 + n*272 + c8*16, &g_ow1t[0][c][n*128 + c8*8]);
    }
    CPA_COMMIT();

    if (tid < NC) {
        float s = 0.f;
        const float* row = xb + tid * Dd;
        #pragma unroll 8
        for (int d = 0; d < Dd; d++) { float v = row[d]; s = fmaf(v, v, s); }
        inorm[tid] = __fdiv_rn(1.f, __fsqrt_rn(s) + EPSF);
    }
    __syncthreads();

    #pragma unroll
    for (int o = tid; o < 512; o += NT) {
        int c = o >> 7, d = o & 127;
        float s = pb2[d];
        const float* ph = ph4 + c*64;
        #pragma unroll 8
        for (int tt = 0; tt < 64; tt++) s = fmaf(ph[tt], pW2[tt*128 + d], s);
        ptok4[o] = s;
    }
    __syncthreads();
    #pragma unroll
    for (int o = tid; o < 1024; o += NT) {
        int c = o >> 8, q = o & 255;
        float s = 0.f;
        const float* pt = ptok4 + c*128;
        #pragma unroll 8
        for (int d = 0; d < 128; d++) s = fmaf(pt[d], fW1[(size_t)(1024 + d)*256 + q], s);
        pcon[o] = s;
    }
    __syncthreads();

    // ---- hid accumulator fragments: 8 warps split 256 cols (nq = wid) ----
    const int nq = wid;            // cols nq*32 .. +31 (4 ntiles), rows 0..31
    float acc[2][4][4];
    #pragma unroll
    for (int mt2 = 0; mt2 < 2; mt2++) {
        int row = mt2*16 + g;
        int c0 = pcx[row], c1 = pcx[row + 8];
        #pragma unroll
        for (int nt = 0; nt < 4; nt++) {
            int q = nq*32 + nt*8 + t2;
            float cs0 = g_csum[q], cs1 = g_csum[q+1];
            acc[mt2][nt][0] = fb1[q]   + pcon[c0*256 + q]     + cs0;
            acc[mt2][nt][1] = fb1[q+1] + pcon[c0*256 + q + 1] + cs1;
            acc[mt2][nt][2] = fb1[q]   + pcon[c1*256 + q]     + cs0;
            acc[mt2][nt][3] = fb1[q+1] + pcon[c1*256 + q + 1] + cs1;
        }
    }

    #pragma unroll 1
    for (int k = 0; k < 8; k++) {
        const int w = mlp_idx[k];
        const u32 bufW = (k & 1) ? (sb + OFF_WS1) : (sb + OFF_WS0);  // W1(k) here
        const u32 bufG = (k & 1) ? (sb + OFF_WS0) : (sb + OFF_WS1);
        const u32* wW = (const u32*)(smc + ((k & 1) ? OFF_WS1 : OFF_WS0));
        const u32* wG = (const u32*)(smc + ((k & 1) ? OFF_WS0 : OFF_WS1));

        // ---- S1: issue G_hi -> bufG; feats -> fh/fl (x from L2) ----
        #pragma unroll
        for (int i = 0; i < 8; i++) {
            int idx = tid + i*NT;               // [256 n][72 k] bf16 panel
            int n = idx >> 3, c8 = idx & 7;
            cpa16(bufG + n*144 + c8*16, &g_gt[k][0][n*64 + c8*8]);
        }
        CPA_COMMIT();

        #pragma unroll
        for (int it = 0; it < 4; it++) {
            int o = tid + it*NT;                // 0..1023 float4
            int p = o >> 5, d4 = (o & 31) * 4;
            int ci = pi[p], cj = pj[p];
            float4 a4 = *(const float4*)(xb + ci*Dd + d4);
            float4 c4 = *(const float4*)(xb + cj*Dd + d4);
            float ni = inorm[ci], nj = inorm[cj];
            float f0 = featf(k, a4.x, c4.x, ni, nj);
            float f1 = featf(k, a4.y, c4.y, ni, nj);
            float f2 = featf(k, a4.z, c4.z, ni, nj);
            float f3 = featf(k, a4.w, c4.w, ni, nj);
            u32 h01, l01, h23, l23;
            split2(f0, f1, h01, l01);
            split2(f2, f3, h23, l23);
            int widx = p*68 + d4/2;
            *(uint2*)(fhw + widx) = make_uint2(h01, h23);
            *(uint2*)(flw + widx) = make_uint2(l01, l23);
        }
        CPA_WAIT0();            // W1(k) (prefetched) + G_hi
        __syncthreads();

        // ---- S2: h = relu(feats @ W1 + b1): 8 warps as 2m x 4n (B = bufW) ----
        {
            const int mt = wid >> 2, nh = wid & 3;
            const int arow = mt*16 + g;
            const u32* w1h = wW;                  // [64][68] u32 rows
            const u32* w1l = wW + 4352;           // +17408B
            float hacc[2][4];
            #pragma unroll
            for (int nt = 0; nt < 2; nt++)
                #pragma unroll
                for (int e = 0; e < 4; e++) hacc[nt][e] = 0.f;
            #pragma unroll 1
            for (int ks = 0; ks < 8; ks++) {
                int base0 = arow*68 + ks*8 + t;
                int base1 = base0 + 8*68;
                u32 ah0 = fhw[base0], ah1 = fhw[base1], ah2 = fhw[base0+4], ah3 = fhw[base1+4];
                u32 al0 = flw[base0], al1 = flw[base1], al2 = flw[base0+4], al3 = flw[base1+4];
                #pragma unroll
                for (int nt = 0; nt < 2; nt++) {
                    int bn = nh*16 + nt*8 + g;
                    int bidx = bn*68 + ks*8 + t;
                    u32 bh0 = w1h[bidx], bh1 = w1h[bidx+4];
                    u32 bl0 = w1l[bidx], bl1 = w1l[bidx+4];
                    mma16816(hacc[nt], ah0, ah1, ah2, ah3, bh0, bh1);
                    mma16816(hacc[nt], al0, al1, al2, al3, bh0, bh1);
                    mma16816(hacc[nt], ah0, ah1, ah2, ah3, bl0, bl1);
                }
            }
            #pragma unroll
            for (int nt = 0; nt < 2; nt++) {
                int col = nh*16 + nt*8 + t2;
                float b0 = ob1[w*64 + col], b1v = ob1[w*64 + col + 1];
                float v0 = hacc[nt][0] + b0, v1 = hacc[nt][1] + b1v;
                float v2 = hacc[nt][2] + b0, v3 = hacc[nt][3] + b1v;
                v0 = v0 > 0.f ? v0 : 0.f; v1 = v1 > 0.f ? v1 : 0.f;
                v2 = v2 > 0.f ? v2 : 0.f; v3 = v3 > 0.f ? v3 : 0.f;
                u32 hp, lp;
                int cw = col/2;
                split2(v0, v1, hp, lp);
                hhw[arow*36 + cw] = hp; hlw[arow*36 + cw] = lp;
                split2(v2, v3, hp, lp);
                hhw[(arow+8)*36 + cw] = hp; hlw[(arow+8)*36 + cw] = lp;
            }
        }
        __syncthreads();

        // ---- S3: issue G_lo -> bufW (W1 dead); hi-terms vs G_hi (B = bufG) ----
        #pragma unroll
        for (int i = 0; i < 8; i++) {
            int idx = tid + i*NT;
            int n = idx >> 3, c8 = idx & 7;
            cpa16(bufW + n*144 + c8*16, &g_gt[k][1][n*64 + c8*8]);
        }
        CPA_COMMIT();
        #pragma unroll 1
        for (int ks = 0; ks < 4; ks++) {
            u32 ah[2][4], al[2][4];
            #pragma unroll
            for (int mt2 = 0; mt2 < 2; mt2++) {
                int row = mt2*16 + g;
                int base0 = row*36 + ks*8 + t;
                int base1 = base0 + 8*36;
                ah[mt2][0] = hhw[base0]; ah[mt2][1] = hhw[base1];
                ah[mt2][2] = hhw[base0+4]; ah[mt2][3] = hhw[base1+4];
                al[mt2][0] = hlw[base0]; al[mt2][1] = hlw[base1];
                al[mt2][2] = hlw[base0+4]; al[mt2][3] = hlw[base1+4];
            }
            #pragma unroll
            for (int nt = 0; nt < 4; nt++) {
                int bn = nq*32 + nt*8 + g;
                int bidx = bn*36 + ks*8 + t;
                u32 bh0 = wG[bidx], bh1 = wG[bidx+4];
                #pragma unroll
                for (int mt2 = 0; mt2 < 2; mt2++) {
                    mma16816(acc[mt2][nt], ah[mt2][0], ah[mt2][1], ah[mt2][2], ah[mt2][3], bh0, bh1);
                    mma16816(acc[mt2][nt], al[mt2][0], al[mt2][1], al[mt2][2], al[mt2][3], bh0, bh1);
                }
            }
        }
        CPA_WAIT0();
        __syncthreads();

        // ---- S4: issue W1(k+1) -> bufG (G_hi dead); lo-term vs G_lo (B = bufW) ----
        if (k < 7) {
            const int wn = mlp_idx[k+1];
            #pragma unroll
            for (int i = 0; i < 8; i++) {
                int idx = tid + i*NT;
                int c = idx >> 10, e = idx & 1023;
                int n = e >> 4, c8 = e & 15;
                cpa16(bufG + c*17408 + n*272 + c8*16, &g_ow1t[wn][c][n*128 + c8*8]);
            }
            CPA_COMMIT();
        }
        #pragma unroll 1
        for (int ks = 0; ks < 4; ks++) {
            u32 ah[2][4];
            #pragma unroll
            for (int mt2 = 0; mt2 < 2; mt2++) {
                int row = mt2*16 + g;
                int base0 = row*36 + ks*8 + t;
                int base1 = base0 + 8*36;
                ah[mt2][0] = hhw[base0]; ah[mt2][1] = hhw[base1];
                ah[mt2][2] = hhw[base0+4]; ah[mt2][3] = hhw[base1+4];
            }
            #pragma unroll
            for (int nt = 0; nt < 4; nt++) {
                int bn = nq*32 + nt*8 + g;
                int bidx = bn*36 + ks*8 + t;
                u32 bl0 = wW[bidx], bl1 = wW[bidx+4];
                #pragma unroll
                for (int mt2 = 0; mt2 < 2; mt2++)
                    mma16816(acc[mt2][nt], ah[mt2][0], ah[mt2][1], ah[mt2][2], ah[mt2][3], bl0, bl1);
            }
        }
        if (k < 7) CPA_WAIT0();
        __syncthreads();
    }

    // ---- F1: hid epilogue -> bf16 panels (alias dead smem); stage fW2 kc0 ----
    u32* hidh = (u32*)(smc + OFF_HIDH);   // [32][132] u32
    u32* hidl = (u32*)(smc + OFF_HIDL);
    #pragma unroll
    for (int i = 0; i < 8; i++) {         // fW2 kc0: hi->WS0, lo->WS1, [128][136] panels
        int idx = tid + i*NT;
        int n = idx >> 4, c8 = idx & 15;
        cpa16(sb + OFF_WS0 + n*272 + c8*16, &g_fw2t[0][n*256 + c8*8]);
        cpa16(sb + OFF_WS1 + n*272 + c8*16, &g_fw2t[1][n*256 + c8*8]);
    }
    CPA_COMMIT();
    #pragma unroll
    for (int mt2 = 0; mt2 < 2; mt2++) {
        #pragma unroll
        for (int nt = 0; nt < 4; nt++) {
            int row = mt2*16 + g;
            float v0 = acc[mt2][nt][0] > 0.f ? acc[mt2][nt][0] : 0.f;
            float v1 = acc[mt2][nt][1] > 0.f ? acc[mt2][nt][1] : 0.f;
            float v2 = acc[mt2][nt][2] > 0.f ? acc[mt2][nt][2] : 0.f;
            float v3 = acc[mt2][nt][3] > 0.f ? acc[mt2][nt][3] : 0.f;
            int cw = nq*16 + nt*4 + t;
            u32 hp, lp;
            split2(v0, v1, hp, lp);
            hidh[row*132 + cw] = hp; hidl[row*132 + cw] = lp;
            split2(v2, v3, hp, lp);
            hidh[(row+8)*132 + cw] = hp; hidl[(row+8)*132 + cw] = lp;
        }
    }
    CPA_WAIT0();
    __syncthreads();

    // ---- F2: out = relu(hid) @ fW2 + fb2 via mma: 8 warps as 2m x 4n(32) ----
    {
        const int mt = wid >> 2, nh = wid & 3;
        const int arow = mt*16 + g;
        float acc2[4][4];
        #pragma unroll
        for (int nt = 0; nt < 4; nt++)
            #pragma unroll
            for (int e = 0; e < 4; e++) acc2[nt][e] = 0.f;
        u32* ws0w = (u32*)(smc + OFF_WS0);
        u32* ws1w = (u32*)(smc + OFF_WS1);

        #pragma unroll 1
        for (int kc = 0; kc < 2; kc++) {
            if (kc == 1) {
                #pragma unroll
                for (int i = 0; i < 8; i++) {
                    int idx = tid + i*NT;
                    int n = idx >> 4, c8 = idx & 15;
                    cpa16(sb + OFF_WS0 + n*272 + c8*16, &g_fw2t[0][n*256 + 128 + c8*8]);
                    cpa16(sb + OFF_WS1 + n*272 + c8*16, &g_fw2t[1][n*256 + 128 + c8*8]);
                }
                CPA_COMMIT();
                CPA_WAIT0();
                __syncthreads();
            }
            #pragma unroll 1
            for (int ks = 0; ks < 8; ks++) {
                int base0 = arow*132 + kc*64 + ks*8 + t;
                int base1 = base0 + 8*132;
                u32 ah0 = hidh[base0], ah1 = hidh[base1], ah2 = hidh[base0+4], ah3 = hidh[base1+4];
                u32 al0 = hidl[base0], al1 = hidl[base1], al2 = hidl[base0+4], al3 = hidl[base1+4];
                #pragma unroll
                for (int nt = 0; nt < 4; nt++) {
                    int bn = nh*32 + nt*8 + g;
                    int bidx = bn*68 + ks*8 + t;
                    u32 bh0 = ws0w[bidx], bh1 = ws0w[bidx+4];
                    u32 bl0 = ws1w[bidx], bl1 = ws1w[bidx+4];
                    mma16816(acc2[nt], ah0, ah1, ah2, ah3, bh0, bh1);
                    mma16816(acc2[nt], al0, al1, al2, al3, bh0, bh1);
                    mma16816(acc2[nt], ah0, ah1, ah2, ah3, bl0, bl1);
                }
            }
            if (kc == 0) __syncthreads();
        }

        // epilogue: + fb2, store to gmem (2016 = 63*32, no tail)
        #pragma unroll
        for (int nt = 0; nt < 4; nt++) {
            int col = nh*32 + nt*8 + t2;
            float b0 = fb2[col], b1v = fb2[col + 1];
            int r0 = arow, r1 = arow + 8;
            float2 v0 = make_float2(acc2[nt][0] + b0, acc2[nt][1] + b1v);
            float2 v1 = make_float2(acc2[nt][2] + b0, acc2[nt][3] + b1v);
            *(float2*)(out + ((size_t)(b*Pp + p0 + r0))*128 + col) = v0;
            *(float2*)(out + ((size_t)(b*Pp + p0 + r1))*128 + col) = v1;
        }
    }
}

extern "C" void kernel_launch(void* const* d_in, const int* in_sizes, int n_in,
                              void* d_out, int out_size) {
    const float* x        = (const float*)d_in[0];
    const int*   presence = (const int*)d_in[1];
    const int*   idx_i    = (const int*)d_in[2];
    const int*   idx_j    = (const int*)d_in[3];
    const float* oW1      = (const float*)d_in[4];
    const float* ob1      = (const float*)d_in[5];
    const float* oW2      = (const float*)d_in[6];
    const float* ob2      = (const float*)d_in[7];
    const float* pW1      = (const float*)d_in[8];
    const float* pb1      = (const float*)d_in[9];
    const float* pW2      = (const float*)d_in[10];
    const float* pb2      = (const float*)d_in[11];
    const float* fW1      = (const float*)d_in[12];
    const float* fb1      = (const float*)d_in[13];
    const float* fW2      = (const float*)d_in[14];
    const float* fb2      = (const float*)d_in[15];

    conv_kernel<<<1024, 256>>>(fW1, oW1, oW2, ob2, fW2);

    cudaFuncSetAttribute(dre_kernel, cudaFuncAttributeMaxDynamicSharedMemorySize, SMEM_BYTES);
    dim3 grid(63, 64);
    dre_kernel<<<grid, NT, SMEM_BYTES>>>(x, presence, idx_i, idx_j,
                                         oW1, ob1, oW2, ob2,
                                         pW1, pb1, pW2, pb2,
                                         fW1, fb1, fW2, fb2,
                                         (float*)d_out);
}

// round 16
// speedup vs baseline: 1.2544x; 1.2544x over previous
#include <cuda_runtime.h>
#include <cuda_bf16.h>
#include <cstdint>

// DynamicRelationshipExtractor — GB300 sm_103a, round 16
// = round 15 with the F2 kc1 A-operand offset fixed (+128B -> +256B; kc1
//   covers q 128..255 = +64 u32 = +256 bytes). All fragment loads ldmatrix.

#define EPSF 1e-6f
#define NT 512

static const int NC = 64;
static const int Dd = 128;
static const int Pp = 2016;
static const int TP = 64;

typedef unsigned long long u64;
typedef unsigned int u32;

__device__ __forceinline__ void mma16816(float* c, u32 a0, u32 a1, u32 a2, u32 a3,
                                         u32 b0, u32 b1) {
    asm volatile(
        "mma.sync.aligned.m16n8k16.row.col.f32.bf16.bf16.f32 "
        "{%0,%1,%2,%3},{%4,%5,%6,%7},{%8,%9},{%0,%1,%2,%3};"
        : "+f"(c[0]), "+f"(c[1]), "+f"(c[2]), "+f"(c[3])
        : "r"(a0), "r"(a1), "r"(a2), "r"(a3), "r"(b0), "r"(b1));
}
__device__ __forceinline__ void ldsm4(u32 &r0, u32 &r1, u32 &r2, u32 &r3, u32 addr) {
    asm volatile("ldmatrix.sync.aligned.m8n8.x4.shared.b16 {%0,%1,%2,%3}, [%4];"
                 : "=r"(r0), "=r"(r1), "=r"(r2), "=r"(r3) : "r"(addr));
}

__device__ __forceinline__ void split2(float a, float b, u32 &hp, u32 &lp) {
    __nv_bfloat16 ha = __float2bfloat16(a), hb_ = __float2bfloat16(b);
    __nv_bfloat16 la = __float2bfloat16(a - __bfloat162float(ha));
    __nv_bfloat16 lb = __float2bfloat16(b - __bfloat162float(hb_));
    hp = ((u32)__bfloat16_as_ushort(hb_) << 16) | (u32)__bfloat16_as_ushort(ha);
    lp = ((u32)__bfloat16_as_ushort(lb)  << 16) | (u32)__bfloat16_as_ushort(la);
}

__device__ __forceinline__ u32 smem_u32(const void* p) {
    u32 a; asm("{ .reg .u64 t; cvta.to.shared.u64 t, %1; cvt.u32.u64 %0, t; }" : "=r"(a) : "l"(p));
    return a;
}
__device__ __forceinline__ void cpa16(u32 dst, const void* src) {
    asm volatile("cp.async.cg.shared.global [%0], [%1], 16;"
                 :: "r"(dst), "l"(__cvta_generic_to_global(src)));
}
#define CPA_COMMIT() asm volatile("cp.async.commit_group;" ::: "memory")
#define CPA_WAIT0()  asm volatile("cp.async.wait_group 0;" ::: "memory")

// precomputed weight images (bf16 hi/lo, B-operand [n][k] layouts)
__device__ __align__(16) __nv_bfloat16 g_ow1t[6][2][8192];   // W1^T: [64 n(j)][128 k(d)]
__device__ __align__(16) __nv_bfloat16 g_gt[8][2][16384];    // G_k^T: [256 n(q)][64 k(j)]
__device__ __align__(16) __nv_bfloat16 g_fw2t[2][32768];     // fW2^T: [128 n(d)][256 k(q)]
__device__ float g_csum[256];                                 // sum_k b2@fW1_k

__global__ void conv_kernel(const float* __restrict__ fW1,
                            const float* __restrict__ oW1,
                            const float* __restrict__ oW2,
                            const float* __restrict__ ob2,
                            const float* __restrict__ fW2) {
    const int mlp_idx[8] = {0, 1, 2, 3, 4, 4, 5, 5};
    int idx = blockIdx.x * blockDim.x + threadIdx.x;   // 0..262143

    if (idx < 131072) {
        int kidx = idx >> 14;
        int e = idx & 16383;
        int q = e & 255, j = e >> 8;
        int w = mlp_idx[kidx];
        const float* w2row = oW2 + (size_t)w*8192 + j*128;
        const float* f1col = fW1 + (size_t)kidx*128*256 + q;
        float s = 0.f;
        #pragma unroll 8
        for (int d = 0; d < 128; d++) s = fmaf(w2row[d], f1col[(size_t)d*256], s);
        __nv_bfloat16 hi = __float2bfloat16(s);
        __nv_bfloat16 lo = __float2bfloat16(s - __bfloat162float(hi));
        g_gt[kidx][0][q*64 + j] = hi;
        g_gt[kidx][1][q*64 + j] = lo;
    }
    if (idx < 49152) {
        int w = idx >> 13;
        int e = idx & 8191;
        int n = e >> 7, kk = e & 127;       // n=j, k=d
        float v = oW1[(size_t)w*8192 + kk*64 + n];
        __nv_bfloat16 hi = __float2bfloat16(v);
        __nv_bfloat16 lo = __float2bfloat16(v - __bfloat162float(hi));
        g_ow1t[w][0][n*128 + kk] = hi;
        g_ow1t[w][1][n*128 + kk] = lo;
    }
    if (idx < 32768) {
        int n = idx >> 8, kk = idx & 255;   // n=d(128), k=q(256)
        float v = fW2[(size_t)kk*128 + n];
        __nv_bfloat16 hi = __float2bfloat16(v);
        __nv_bfloat16 lo = __float2bfloat16(v - __bfloat162float(hi));
        g_fw2t[0][n*256 + kk] = hi;
        g_fw2t[1][n*256 + kk] = lo;
    }
    if (idx < 256) {
        int q = idx;
        float s = 0.f;
        for (int kk = 0; kk < 8; kk++) {
            int w = mlp_idx[kk];
            const float* b2r = ob2 + w*128;
            const float* f1c = fW1 + (size_t)kk*128*256 + q;
            #pragma unroll 8
            for (int d = 0; d < 128; d++) s = fmaf(b2r[d], f1c[(size_t)d*256], s);
        }
        g_csum[q] = s;
    }
}

// ---- shared layout (BYTE offsets) ----
#define OFF_XS     0          // 32768 (fp32 x[b])
#define OFF_FH     32768      // [64][136] bf16 = 17408 (272B rows)
#define OFF_FL     50176      // 17408 -> 67584
#define OFF_HH     67584      // [64][72] bf16 = 9216 (144B rows)
#define OFF_HL     76800      // 9216 -> 86016
#define OFF_WS0    86016      // 36864 -> 122880
#define OFF_WS1    122880     // 36864 -> 159744
#define OFF_WS2    159744     // 36864 -> 196608
#define OFF_PCON   196608     // 1024 fl -> 200704
#define OFF_PTOK4  200704     // 512 fl -> 202752
#define OFF_PH4    202752     // 256 fl -> 203776
#define OFF_INORM  203776     // 64 fl -> 204032
#define OFF_INTS   204032     // 3*64 int -> 204800
#define SMEM_BYTES 204800
// hid bf16 panels alias [0, 67584): hi [64][264] (528B rows) at 0, lo at 33792
#define OFF_HIDH   0
#define OFF_HIDL   33792

__device__ __forceinline__ float featf(int k, float a, float c, float ni, float nj) {
    switch (k) {
        case 0: return a * c;
        case 1: return a + c;
        case 2: return (a * ni) * (c * nj);
        case 3: return fabsf(a - c);
        case 4: return a - c;
        case 5: return c - a;
        case 6: return __fdiv_rn(a, c + EPSF);
        default: return __fdiv_rn(c, a + EPSF);
    }
}

__global__ void __launch_bounds__(NT, 1)
dre_kernel(const float* __restrict__ x, const int* __restrict__ presence,
           const int* __restrict__ idx_i, const int* __restrict__ idx_j,
           const float* __restrict__ oW1, const float* __restrict__ ob1,
           const float* __restrict__ oW2, const float* __restrict__ ob2,
           const float* __restrict__ pW1, const float* __restrict__ pb1,
           const float* __restrict__ pW2, const float* __restrict__ pb2,
           const float* __restrict__ fW1, const float* __restrict__ fb1,
           const float* __restrict__ fW2, const float* __restrict__ fb2,
           float* __restrict__ out)
{
    extern __shared__ float sm[];
    char*  smc   = (char*)sm;
    float* xs    = (float*)(smc + OFF_XS);
    u32*   fhw   = (u32*)(smc + OFF_FH);
    u32*   flw   = (u32*)(smc + OFF_FL);
    u32*   hhw   = (u32*)(smc + OFF_HH);
    u32*   hlw   = (u32*)(smc + OFF_HL);
    float* pcon  = (float*)(smc + OFF_PCON);
    float* ptok4 = (float*)(smc + OFF_PTOK4);
    float* ph4   = (float*)(smc + OFF_PH4);
    float* inorm = (float*)(smc + OFF_INORM);
    int*   pi    = (int*)(smc + OFF_INTS);
    int*   pj    = pi + 64;
    int*   pcx   = pj + 64;

    const int tid = threadIdx.x;
    const int b   = blockIdx.x >> 5;
    const int p0  = (blockIdx.x & 31) * TP;
    const int wid = tid >> 5, lane = tid & 31;
    const int g   = lane >> 2;          // frag row group 0..7
    const int t   = lane & 3;           // frag k-word 0..3
    const int t2  = t * 2;
    const int lrow  = lane & 15;        // ldmatrix row within 16-row tile
    const int lcolb = (lane >> 4) * 16; // ldmatrix k-half byte offset
    const u32 sb  = smem_u32(sm);

    const int mlp_idx[8] = {0, 1, 2, 3, 4, 4, 5, 5};

    // ---- load x[b] ----
    {
        const float4* src = (const float4*)(x + (size_t)b * NC * Dd);
        float4* dst = (float4*)xs;
        #pragma unroll
        for (int i = 0; i < 4; i++) dst[tid + i*NT] = src[tid + i*NT];
    }
    if (tid < TP) {
        int pp = p0 + tid; if (pp >= Pp) pp = Pp - 1;
        int ii = idx_i[pp], jj = idx_j[pp];
        pi[tid] = ii; pj[tid] = jj;
        int pa = presence[b*NC + ii], pb_ = presence[b*NC + jj];
        pcx[tid] = pa ? (pb_ ? 0 : 1) : (pb_ ? 2 : 3);
    }
    if (tid < 256) {
        int c = tid >> 6, tt = tid & 63;
        float v = pW1[c*64 + tt] + pb1[tt];
        ph4[tid] = v > 0.f ? v : 0.f;
    }
    // prologue prefetch: W1(0) -> WS0
    #pragma unroll
    for (int i = 0; i < 4; i++) {
        int idx = tid + i*NT;               // 0..2047
        int c = idx >> 10, e = idx & 1023;
        int n = e >> 4, c8 = e & 15;
        cpa16(sb + OFF_WS0 + c*17408 + n*272 + c8*16, &g_ow1t[0][c][n*128 + c8*8]);
    }
    CPA_COMMIT();
    __syncthreads();

    if (tid < NC) {
        float s = 0.f;
        const float* row = xs + tid * Dd;
        #pragma unroll 8
        for (int d = 0; d < Dd; d++) { float v = row[d]; s = fmaf(v, v, s); }
        inorm[tid] = __fdiv_rn(1.f, __fsqrt_rn(s) + EPSF);
    }
    if (tid < 512) {
        int o = tid;
        int c = o >> 7, d = o & 127;
        float s = pb2[d];
        const float* ph = ph4 + c*64;
        #pragma unroll 8
        for (int tt = 0; tt < 64; tt++) s = fmaf(ph[tt], pW2[tt*128 + d], s);
        ptok4[o] = s;
    }
    __syncthreads();
    for (int o = tid; o < 1024; o += NT) {
        int c = o >> 8, q = o & 255;
        float s = 0.f;
        const float* pt = ptok4 + c*128;
        #pragma unroll 8
        for (int d = 0; d < 128; d++) s = fmaf(pt[d], fW1[(size_t)(1024 + d)*256 + q], s);
        pcon[o] = s;
    }
    __syncthreads();

    // ---- hid accumulator fragments: 16 warps as 2m x 8n ----
    const int mh = wid & 1;        // rows mh*32 .. +31
    const int nq = wid >> 1;       // cols nq*32 .. +31 (4 ntiles)
    float acc[2][4][4];
    #pragma unroll
    for (int mt2 = 0; mt2 < 2; mt2++) {
        int row = mh*32 + mt2*16 + g;
        int c0 = pcx[row], c1 = pcx[row + 8];
        #pragma unroll
        for (int nt = 0; nt < 4; nt++) {
            int q = nq*32 + nt*8 + t2;
            float cs0 = g_csum[q], cs1 = g_csum[q+1];
            acc[mt2][nt][0] = fb1[q]   + pcon[c0*256 + q]     + cs0;
            acc[mt2][nt][1] = fb1[q+1] + pcon[c0*256 + q + 1] + cs1;
            acc[mt2][nt][2] = fb1[q]   + pcon[c1*256 + q]     + cs0;
            acc[mt2][nt][3] = fb1[q+1] + pcon[c1*256 + q + 1] + cs1;
        }
    }

    #pragma unroll 1
    for (int k = 0; k < 8; k++) {
        const int w = mlp_idx[k];

        // ---- S1: issue G_hi -> WS1, G_lo -> WS2; feats -> fh/fl ----
        #pragma unroll
        for (int i = 0; i < 4; i++) {
            int idx = tid + i*NT;               // [256 n][72 k] bf16 panels (144B rows)
            int n = idx >> 3, c8 = idx & 7;
            cpa16(sb + OFF_WS1 + n*144 + c8*16, &g_gt[k][0][n*64 + c8*8]);
            cpa16(sb + OFF_WS2 + n*144 + c8*16, &g_gt[k][1][n*64 + c8*8]);
        }
        CPA_COMMIT();

        #pragma unroll 1
        for (int it = 0; it < 4; it++) {
            int o = tid + it*NT;
            int p = o >> 5, d4 = (o & 31) * 4;
            int ci = pi[p], cj = pj[p];
            float4 a4 = *(const float4*)(xs + ci*Dd + d4);
            float4 c4 = *(const float4*)(xs + cj*Dd + d4);
            float ni = inorm[ci], nj = inorm[cj];
            float f0 = featf(k, a4.x, c4.x, ni, nj);
            float f1 = featf(k, a4.y, c4.y, ni, nj);
            float f2 = featf(k, a4.z, c4.z, ni, nj);
            float f3 = featf(k, a4.w, c4.w, ni, nj);
            u32 h01, l01, h23, l23;
            split2(f0, f1, h01, l01);
            split2(f2, f3, h23, l23);
            int widx = p*68 + d4/2;
            *(uint2*)(fhw + widx) = make_uint2(h01, h23);
            *(uint2*)(flw + widx) = make_uint2(l01, l23);
        }
        CPA_WAIT0();            // W1(k) (prefetched last phase) + G panels
        __syncthreads();

        // ---- S2: h = relu(feats @ W1 + b1): 16 warps as 4m x 4n (ldmatrix) ----
        {
            const int mt = wid >> 2, nh = wid & 3;
            const int arow = mt*16 + g;
            u32 aAh = sb + OFF_FH  + (u32)(mt*16 + lrow)*272 + lcolb;
            u32 aAl = sb + OFF_FL  + (u32)(mt*16 + lrow)*272 + lcolb;
            u32 aBh = sb + OFF_WS0 + (u32)(nh*16 + lrow)*272 + lcolb;
            u32 aBl = aBh + 17408;
            float hacc[2][4];
            #pragma unroll
            for (int nt = 0; nt < 2; nt++)
                #pragma unroll
                for (int e = 0; e < 4; e++) hacc[nt][e] = 0.f;
            #pragma unroll 1
            for (int ks = 0; ks < 8; ks++) {
                u32 ah0, ah1, ah2, ah3, al0, al1, al2, al3;
                u32 b00, b01, b10, b11, c00, c01, c10, c11;
                ldsm4(ah0, ah1, ah2, ah3, aAh);
                ldsm4(al0, al1, al2, al3, aAl);
                ldsm4(b00, b01, b10, b11, aBh);   // b0(nt0), b0(nt1), b1(nt0), b1(nt1)
                ldsm4(c00, c01, c10, c11, aBl);
                mma16816(hacc[0], ah0, ah1, ah2, ah3, b00, b10);
                mma16816(hacc[0], al0, al1, al2, al3, b00, b10);
                mma16816(hacc[0], ah0, ah1, ah2, ah3, c00, c10);
                mma16816(hacc[1], ah0, ah1, ah2, ah3, b01, b11);
                mma16816(hacc[1], al0, al1, al2, al3, b01, b11);
                mma16816(hacc[1], ah0, ah1, ah2, ah3, c01, c11);
                aAh += 32; aAl += 32; aBh += 32; aBl += 32;
            }
            #pragma unroll
            for (int nt = 0; nt < 2; nt++) {
                int col = nh*16 + nt*8 + t2;
                float b0 = ob1[w*64 + col], b1v = ob1[w*64 + col + 1];
                float v0 = hacc[nt][0] + b0, v1 = hacc[nt][1] + b1v;
                float v2 = hacc[nt][2] + b0, v3 = hacc[nt][3] + b1v;
                v0 = v0 > 0.f ? v0 : 0.f; v1 = v1 > 0.f ? v1 : 0.f;
                v2 = v2 > 0.f ? v2 : 0.f; v3 = v3 > 0.f ? v3 : 0.f;
                u32 hp, lp;
                int cw = col/2;
                split2(v0, v1, hp, lp);
                hhw[arow*36 + cw] = hp; hlw[arow*36 + cw] = lp;
                split2(v2, v3, hp, lp);
                hhw[(arow+8)*36 + cw] = hp; hlw[(arow+8)*36 + cw] = lp;
            }
        }
        __syncthreads();

        // ---- S3: prefetch W1(k+1) -> WS0; merged hid GEMM (3 terms, ldmatrix) ----
        if (k < 7) {
            const int wn = mlp_idx[k+1];
            #pragma unroll
            for (int i = 0; i < 4; i++) {
                int idx = tid + i*NT;
                int c = idx >> 10, e = idx & 1023;
                int n = e >> 4, c8 = e & 15;
                cpa16(sb + OFF_WS0 + c*17408 + n*272 + c8*16, &g_ow1t[wn][c][n*128 + c8*8]);
            }
            CPA_COMMIT();
        }
        {
            u32 aA0h = sb + OFF_HH  + (u32)(mh*32 + lrow)*144 + lcolb;
            u32 aA1h = aA0h + 16*144;
            u32 aA0l = sb + OFF_HL  + (u32)(mh*32 + lrow)*144 + lcolb;
            u32 aA1l = aA0l + 16*144;
            u32 aB0h = sb + OFF_WS1 + (u32)(nq*32 + lrow)*144 + lcolb;   // nt0/1
            u32 aB1h = aB0h + 16*144;                                     // nt2/3
            u32 aB0l = sb + OFF_WS2 + (u32)(nq*32 + lrow)*144 + lcolb;
            u32 aB1l = aB0l + 16*144;
            #pragma unroll 1
            for (int ks = 0; ks < 4; ks++) {
                u32 ah[2][4], al[2][4];
                ldsm4(ah[0][0], ah[0][1], ah[0][2], ah[0][3], aA0h);
                ldsm4(ah[1][0], ah[1][1], ah[1][2], ah[1][3], aA1h);
                ldsm4(al[0][0], al[0][1], al[0][2], al[0][3], aA0l);
                ldsm4(al[1][0], al[1][1], al[1][2], al[1][3], aA1l);
                u32 bh[4][2], bl[4][2];
                ldsm4(bh[0][0], bh[1][0], bh[0][1], bh[1][1], aB0h);  // b0/b1 of nt0,nt1
                ldsm4(bh[2][0], bh[3][0], bh[2][1], bh[3][1], aB1h);  // nt2,nt3
                ldsm4(bl[0][0], bl[1][0], bl[0][1], bl[1][1], aB0l);
                ldsm4(bl[2][0], bl[3][0], bl[2][1], bl[3][1], aB1l);
                #pragma unroll
                for (int nt = 0; nt < 4; nt++) {
                    #pragma unroll
                    for (int mt2 = 0; mt2 < 2; mt2++) {
                        mma16816(acc[mt2][nt], ah[mt2][0], ah[mt2][1], ah[mt2][2], ah[mt2][3], bh[nt][0], bh[nt][1]);
                        mma16816(acc[mt2][nt], al[mt2][0], al[mt2][1], al[mt2][2], al[mt2][3], bh[nt][0], bh[nt][1]);
                        mma16816(acc[mt2][nt], ah[mt2][0], ah[mt2][1], ah[mt2][2], ah[mt2][3], bl[nt][0], bl[nt][1]);
                    }
                }
                aA0h += 32; aA1h += 32; aA0l += 32; aA1l += 32;
                aB0h += 32; aB1h += 32; aB0l += 32; aB1l += 32;
            }
        }
        CPA_WAIT0();
        __syncthreads();
    }

    // ---- F1: hid epilogue -> bf16 hi/lo panels; stage fW2 kc0 hi/lo + kc1 hi ----
    u32* hidh = (u32*)(smc + OFF_HIDH);   // [64][132] u32 (528B rows)
    u32* hidl = (u32*)(smc + OFF_HIDL);
    #pragma unroll
    for (int i = 0; i < 4; i++) {         // [128][136] bf16 panels (272B rows)
        int idx = tid + i*NT;
        int n = idx >> 4, c8 = idx & 15;
        cpa16(sb + OFF_WS0 + n*272 + c8*16, &g_fw2t[0][n*256 + c8*8]);
        cpa16(sb + OFF_WS1 + n*272 + c8*16, &g_fw2t[1][n*256 + c8*8]);
        cpa16(sb + OFF_WS2 + n*272 + c8*16, &g_fw2t[0][n*256 + 128 + c8*8]);
    }
    CPA_COMMIT();
    #pragma unroll
    for (int mt2 = 0; mt2 < 2; mt2++) {
        #pragma unroll
        for (int nt = 0; nt < 4; nt++) {
            int row = mh*32 + mt2*16 + g;
            float v0 = acc[mt2][nt][0] > 0.f ? acc[mt2][nt][0] : 0.f;
            float v1 = acc[mt2][nt][1] > 0.f ? acc[mt2][nt][1] : 0.f;
            float v2 = acc[mt2][nt][2] > 0.f ? acc[mt2][nt][2] : 0.f;
            float v3 = acc[mt2][nt][3] > 0.f ? acc[mt2][nt][3] : 0.f;
            int cw = nq*16 + nt*4 + t;
            u32 hp, lp;
            split2(v0, v1, hp, lp);
            hidh[row*132 + cw] = hp; hidl[row*132 + cw] = lp;
            split2(v2, v3, hp, lp);
            hidh[(row+8)*132 + cw] = hp; hidl[(row+8)*132 + cw] = lp;
        }
    }
    CPA_WAIT0();
    __syncthreads();

    // ---- F2: out = relu(hid) @ fW2 + fb2 via mma: 4m x 4n(32), ldmatrix ----
    {
        const int mt = wid >> 2, nh = wid & 3;
        const int arow = mt*16 + g;
        float acc2[4][4];
        #pragma unroll
        for (int nt = 0; nt < 4; nt++)
            #pragma unroll
            for (int e = 0; e < 4; e++) acc2[nt][e] = 0.f;

        // kc0: 3-term (hi = WS0, lo = WS1)
        {
            u32 aAh = sb + OFF_HIDH + (u32)(mt*16 + lrow)*528 + lcolb;
            u32 aAl = sb + OFF_HIDL + (u32)(mt*16 + lrow)*528 + lcolb;
            u32 aB0h = sb + OFF_WS0 + (u32)(nh*32 + lrow)*272 + lcolb;
            u32 aB1h = aB0h + 16*272;
            u32 aB0l = sb + OFF_WS1 + (u32)(nh*32 + lrow)*272 + lcolb;
            u32 aB1l = aB0l + 16*272;
            #pragma unroll 1
            for (int ks = 0; ks < 8; ks++) {
                u32 ah0, ah1, ah2, ah3, al0, al1, al2, al3;
                ldsm4(ah0, ah1, ah2, ah3, aAh);
                ldsm4(al0, al1, al2, al3, aAl);
                u32 bh[4][2], bl[4][2];
                ldsm4(bh[0][0], bh[1][0], bh[0][1], bh[1][1], aB0h);
                ldsm4(bh[2][0], bh[3][0], bh[2][1], bh[3][1], aB1h);
                ldsm4(bl[0][0], bl[1][0], bl[0][1], bl[1][1], aB0l);
                ldsm4(bl[2][0], bl[3][0], bl[2][1], bl[3][1], aB1l);
                #pragma unroll
                for (int nt = 0; nt < 4; nt++) {
                    mma16816(acc2[nt], ah0, ah1, ah2, ah3, bh[nt][0], bh[nt][1]);
                    mma16816(acc2[nt], al0, al1, al2, al3, bh[nt][0], bh[nt][1]);
                    mma16816(acc2[nt], ah0, ah1, ah2, ah3, bl[nt][0], bl[nt][1]);
                }
                aAh += 32; aAl += 32; aB0h += 32; aB1h += 32; aB0l += 32; aB1l += 32;
            }
        }
        __syncthreads();   // everyone done reading WS0/WS1 (kc0 panels)

        // stage kc1 lo -> WS0 (overlaps with kc1 hi-term mma below)
        #pragma unroll
        for (int i = 0; i < 4; i++) {
            int idx = tid + i*NT;
            int n = idx >> 4, c8 = idx & 15;
            cpa16(sb + OFF_WS0 + n*272 + c8*16, &g_fw2t[1][n*256 + 128 + c8*8]);
        }
        CPA_COMMIT();

        // kc1 hi-terms (hi = WS2); A offset +256B = q 128..255
        {
            u32 aAh = sb + OFF_HIDH + (u32)(mt*16 + lrow)*528 + 256 + lcolb;
            u32 aAl = sb + OFF_HIDL + (u32)(mt*16 + lrow)*528 + 256 + lcolb;
            u32 aB0h = sb + OFF_WS2 + (u32)(nh*32 + lrow)*272 + lcolb;
            u32 aB1h = aB0h + 16*272;
            #pragma unroll 1
            for (int ks = 0; ks < 8; ks++) {
                u32 ah0, ah1, ah2, ah3, al0, al1, al2, al3;
                ldsm4(ah0, ah1, ah2, ah3, aAh);
                ldsm4(al0, al1, al2, al3, aAl);
                u32 bh[4][2];
                ldsm4(bh[0][0], bh[1][0], bh[0][1], bh[1][1], aB0h);
                ldsm4(bh[2][0], bh[3][0], bh[2][1], bh[3][1], aB1h);
                #pragma unroll
                for (int nt = 0; nt < 4; nt++) {
                    mma16816(acc2[nt], ah0, ah1, ah2, ah3, bh[nt][0], bh[nt][1]);
                    mma16816(acc2[nt], al0, al1, al2, al3, bh[nt][0], bh[nt][1]);
                }
                aAh += 32; aAl += 32; aB0h += 32; aB1h += 32;
            }
        }
        CPA_WAIT0();
        __syncthreads();

        // kc1 lo-term (lo = WS0)
        {
            u32 aAh = sb + OFF_HIDH + (u32)(mt*16 + lrow)*528 + 256 + lcolb;
            u32 aB0l = sb + OFF_WS0 + (u32)(nh*32 + lrow)*272 + lcolb;
            u32 aB1l = aB0l + 16*272;
            #pragma unroll 1
            for (int ks = 0; ks < 8; ks++) {
                u32 ah0, ah1, ah2, ah3;
                ldsm4(ah0, ah1, ah2, ah3, aAh);
                u32 bl[4][2];
                ldsm4(bl[0][0], bl[1][0], bl[0][1], bl[1][1], aB0l);
                ldsm4(bl[2][0], bl[3][0], bl[2][1], bl[3][1], aB1l);
                #pragma unroll
                for (int nt = 0; nt < 4; nt++)
                    mma16816(acc2[nt], ah0, ah1, ah2, ah3, bl[nt][0], bl[nt][1]);
                aAh += 32; aB0l += 32; aB1l += 32;
            }
        }

        // epilogue: + fb2, store to gmem
        #pragma unroll
        for (int nt = 0; nt < 4; nt++) {
            int col = nh*32 + nt*8 + t2;
            float b0 = fb2[col], b1v = fb2[col + 1];
            int r0 = mt*16 + g, r1 = r0 + 8;
            if (p0 + r0 < Pp) {
                float2 v = make_float2(acc2[nt][0] + b0, acc2[nt][1] + b1v);
                *(float2*)(out + ((size_t)(b*Pp + p0 + r0))*128 + col) = v;
            }
            if (p0 + r1 < Pp) {
                float2 v = make_float2(acc2[nt][2] + b0, acc2[nt][3] + b1v);
                *(float2*)(out + ((size_t)(b*Pp + p0 + r1))*128 + col) = v;
            }
        }
    }
}

extern "C" void kernel_launch(void* const* d_in, const int* in_sizes, int n_in,
                              void* d_out, int out_size) {
    const float* x        = (const float*)d_in[0];
    const int*   presence = (const int*)d_in[1];
    const int*   idx_i    = (const int*)d_in[2];
    const int*   idx_j    = (const int*)d_in[3];
    const float* oW1      = (const float*)d_in[4];
    const float* ob1      = (const float*)d_in[5];
    const float* oW2      = (const float*)d_in[6];
    const float* ob2      = (const float*)d_in[7];
    const float* pW1      = (const float*)d_in[8];
    const float* pb1      = (const float*)d_in[9];
    const float* pW2      = (const float*)d_in[10];
    const float* pb2      = (const float*)d_in[11];
    const float* fW1      = (const float*)d_in[12];
    const float* fb1      = (const float*)d_in[13];
    const float* fW2      = (const float*)d_in[14];
    const float* fb2      = (const float*)d_in[15];

    conv_kernel<<<1024, 256>>>(fW1, oW1, oW2, ob2, fW2);

    cudaFuncSetAttribute(dre_kernel, cudaFuncAttributeMaxDynamicSharedMemorySize, SMEM_BYTES);
    dre_kernel<<<2048, NT, SMEM_BYTES>>>(x, presence, idx_i, idx_j,
                                         oW1, ob1, oW2, ob2,
                                         pW1, pb1, pW2, pb2,
                                         fW1, fb1, fW2, fb2,
                                         (float*)d_out);
}